// round 14
// baseline (speedup 1.0000x reference)
#include <cuda_runtime.h>
#include <cuda_fp16.h>
#include <math.h>
#include <cstdint>

// Problem constants
#define BB 8
#define HH 37
#define WW 37
#define NN (HH * WW)          // 1369
#define CC 1024
#define MM (BB * NN)          // 10952
#define NHEADS 8
#define HD 128
#define NPTS 8
#define K1 1024               // 1-term fp16 (q, k, out GEMMs)
#define K2 2048               // [Ah|Al] activation layout (off GEMM aliases term2 -> term0)
#define K3 3072               // off GEMM logical K (B = [Bh|Bh|Bl])
#define NCK1 (K1 / 64)        // 16
#define NCK3 (K3 / 64)        // 48
#define STAGES 3
#define STAGE_BYTES 32768     // A 16K + B 16K
#define SMEM_SZ (STAGES * STAGE_BYTES)   // 96KB -> 2 CTAs/SM
#define MTILES 86             // ceil(MM/128)
#define ACT_BLKS 5476         // MM*128/256
#define SAMP_BLOCKS 5476      // MM*NHEADS/16 (exact)
#define GEMM_BLOCKS (8 * MTILES)  // 688

// ---------------------------------------------------------------------------
// Scratch
// ---------------------------------------------------------------------------
__device__ __half g_aq[MM * K2];      // query [Ah|Al] (q uses K1 prefix, off aliases chunks)
__device__ __half g_ak[MM * K1];      // ref [Ah]; reused as attn [Ah]
__device__ __half g_bop_q[CC * K1];   // Wq [Bh]
__device__ __half g_bop_k[CC * K1];   // Wkv[:, :C] [Bh]
__device__ __half g_bop_o[CC * K1];   // Wout [Bh]
__device__ __half g_bop_f[128 * K3];  // Woff [Bh|Bh|Bl]
__device__ __half g_q[MM * CC];       // q in fp16
__device__ __half g_k[MM * CC];       // k in fp16
__device__ float  g_offp[MM * 128];
__device__ int    g_cnt[MTILES];      // per-mtile sampling-completion counters

// ---------------------------------------------------------------------------
__device__ __forceinline__ uint32_t smem_u32(const void* p) {
    uint32_t a;
    asm("{ .reg .u64 t; cvta.to.shared.u64 t, %1; cvt.u32.u64 %0, t; }" : "=r"(a) : "l"(p));
    return a;
}
__device__ __forceinline__ void cp16(uint32_t dst, const void* src, bool valid) {
    int sz = valid ? 16 : 0;
    asm volatile("cp.async.cg.shared.global [%0], [%1], 16, %2;"
                 :: "r"(dst), "l"(src), "r"(sz) : "memory");
}
#define CP_COMMIT() asm volatile("cp.async.commit_group;" ::: "memory")
#define CP_WAIT1()  asm volatile("cp.async.wait_group 1;" ::: "memory")

__device__ __forceinline__ void ldsm4(uint32_t* r, uint32_t addr) {
    asm volatile("ldmatrix.sync.aligned.m8n8.x4.shared.b16 {%0,%1,%2,%3}, [%4];"
                 : "=r"(r[0]), "=r"(r[1]), "=r"(r[2]), "=r"(r[3]) : "r"(addr));
}
__device__ __forceinline__ void mma16816(float* c, const uint32_t* a, const uint32_t* b) {
    asm volatile(
        "mma.sync.aligned.m16n8k16.row.col.f32.f16.f16.f32 "
        "{%0,%1,%2,%3},{%4,%5,%6,%7},{%8,%9},{%0,%1,%2,%3};"
        : "+f"(c[0]), "+f"(c[1]), "+f"(c[2]), "+f"(c[3])
        : "r"(a[0]), "r"(a[1]), "r"(a[2]), "r"(a[3]), "r"(b[0]), "r"(b[1]));
}

// ---------------------------------------------------------------------------
// GEMM body (proven): CTA 128x128, 8 warps 64x32, 3-stage cp.async,
// ONE sync per chunk. ka_wrap: A-chunk aliasing (off GEMM term2 -> term0).
// ---------------------------------------------------------------------------
template <typename OutT>
__device__ __forceinline__
void gemm_body(const __half* __restrict__ A, int lda,
               const __half* __restrict__ B, int ldb,
               const float* __restrict__ bias, OutT* __restrict__ C,
               int ldc, int m0, int col0, int nchunk, int ka_wrap, char* smem) {
    const uint32_t sb0 = smem_u32(smem);
    const int tid = threadIdx.x, wid = tid >> 5, lane = tid & 31;
    const __half* Bc0 = B + (size_t)col0 * ldb;

    auto load_stage = [&](int ck, int stage) {
        const uint32_t sa = sb0 + stage * STAGE_BYTES;
        const int ca = (ck >= ka_wrap) ? ck - ka_wrap : ck;
        const __half* Ac = A + ca * 64;
        const __half* Bc = Bc0 + ck * 64;
#pragma unroll
        for (int i = 0; i < 4; i++) {
            int id = tid + i * 256;
            int row = id >> 3, c16 = id & 7;
            int gr = m0 + row;
            bool v = gr < MM;
            int grc = v ? gr : (MM - 1);
            uint32_t dst = sa + row * 128 + (((uint32_t)c16 ^ (row & 7)) << 4);
            cp16(dst, Ac + (size_t)grc * lda + c16 * 8, v);
        }
#pragma unroll
        for (int i = 0; i < 4; i++) {
            int id = tid + i * 256;
            int row = id >> 3, c16 = id & 7;
            uint32_t dst = sa + 16384 + row * 128 + (((uint32_t)c16 ^ (row & 7)) << 4);
            cp16(dst, Bc + (size_t)row * ldb + c16 * 8, true);
        }
        CP_COMMIT();
    };

    float acc[4][4][4];
#pragma unroll
    for (int mt = 0; mt < 4; mt++)
#pragma unroll
        for (int nt = 0; nt < 4; nt++)
#pragma unroll
            for (int j = 0; j < 4; j++) acc[mt][nt][j] = 0.0f;

    load_stage(0, 0);
    load_stage(1, 1);

    const int wm = (wid & 1) * 64;
    const int wn = (wid >> 1) * 32;

    for (int c = 0; c < nchunk; c++) {
        CP_WAIT1();
        __syncthreads();
        if (c + 2 < nchunk) load_stage(c + 2, (c + 2) % STAGES);
        else CP_COMMIT();

        const uint32_t sa = sb0 + (c % STAGES) * STAGE_BYTES;
        const uint32_t sbB = sa + 16384;

#pragma unroll
        for (int ks = 0; ks < 4; ks++) {
            uint32_t af[4][4];
#pragma unroll
            for (int mt = 0; mt < 4; mt++) {
                int row = wm + mt * 16 + (lane & 15);
                uint32_t c16 = (uint32_t)(ks * 2 + (lane >> 4)) ^ (row & 7);
                ldsm4(af[mt], sa + row * 128 + (c16 << 4));
            }
            uint32_t bf[4][2];
#pragma unroll
            for (int nt2 = 0; nt2 < 2; nt2++) {
                int group = lane >> 3;
                int nrow = wn + nt2 * 16 + (group >> 1) * 8 + (lane & 7);
                uint32_t c16 = (uint32_t)(ks * 2 + (group & 1)) ^ (nrow & 7);
                uint32_t r[4];
                ldsm4(r, sbB + nrow * 128 + (c16 << 4));
                bf[nt2 * 2][0] = r[0]; bf[nt2 * 2][1] = r[1];
                bf[nt2 * 2 + 1][0] = r[2]; bf[nt2 * 2 + 1][1] = r[3];
            }
#pragma unroll
            for (int mt = 0; mt < 4; mt++)
#pragma unroll
                for (int nt = 0; nt < 4; nt++)
                    mma16816(acc[mt][nt], af[mt], bf[nt]);
        }
    }
    __syncthreads();

    const int lr = lane >> 2, lc = (lane & 3) * 2;
#pragma unroll
    for (int mt = 0; mt < 4; mt++) {
#pragma unroll
        for (int nt = 0; nt < 4; nt++) {
            int r0 = m0 + wm + mt * 16 + lr;
            int cb = col0 + wn + nt * 8 + lc;
            float b0 = bias[cb], b1 = bias[cb + 1];
            if (r0 < MM) {
                if (sizeof(OutT) == 2) {
                    __half2 v = __floats2half2_rn(acc[mt][nt][0] + b0, acc[mt][nt][1] + b1);
                    *reinterpret_cast<__half2*>((__half*)C + (size_t)r0 * ldc + cb) = v;
                } else {
                    float2 v = make_float2(acc[mt][nt][0] + b0, acc[mt][nt][1] + b1);
                    *reinterpret_cast<float2*>((float*)C + (size_t)r0 * ldc + cb) = v;
                }
            }
            int r1 = r0 + 8;
            if (r1 < MM) {
                if (sizeof(OutT) == 2) {
                    __half2 v = __floats2half2_rn(acc[mt][nt][2] + b0, acc[mt][nt][3] + b1);
                    *reinterpret_cast<__half2*>((__half*)C + (size_t)r1 * ldc + cb) = v;
                } else {
                    float2 v = make_float2(acc[mt][nt][2] + b0, acc[mt][nt][3] + b1);
                    *reinterpret_cast<float2*>((float*)C + (size_t)r1 * ldc + cb) = v;
                }
            }
        }
    }
}

// Merged off + q + k GEMM. t = bx / MTILES:
// t == 0: off (K3 logical, A aliased mod 32); t in [1,9): q; t in [9,17): k.
__global__ __launch_bounds__(256)
void gemm3(const __half* __restrict__ Aq, const __half* __restrict__ Ak,
           const __half* __restrict__ Bq, const __half* __restrict__ Bk,
           const __half* __restrict__ Bf,
           const float* __restrict__ bq, const float* __restrict__ bkv,
           const float* __restrict__ boff,
           __half* __restrict__ Cq, __half* __restrict__ Ck, float* __restrict__ Coff) {
    extern __shared__ char smem[];
    const int bx = blockIdx.x;
    const int t = bx / MTILES;
    const int m0 = (bx % MTILES) * 128;
    if (t == 0) {
        gemm_body<float>(Aq, K2, Bf, K3, boff, Coff, 128, m0, 0, NCK3, 32, smem);
    } else if (t < 9) {
        gemm_body<__half>(Aq, K2, Bq, K1, bq, Cq, CC, m0, (t - 1) * 128, NCK1, 9999, smem);
    } else {
        gemm_body<__half>(Ak, K1, Bk, K1, bkv, Ck, CC, m0, (t - 9) * 128, NCK1, 9999, smem);
    }
}

// ---------------------------------------------------------------------------
// ALL conversions in one launch; also zeroes per-tile counters (every replay).
// ---------------------------------------------------------------------------
__global__ __launch_bounds__(256)
void conv_all(const float* __restrict__ Wq, const float* __restrict__ Wkv,
              const float* __restrict__ Wout, const float* __restrict__ Woff,
              __half* __restrict__ Oq, __half* __restrict__ Ok,
              __half* __restrict__ Oo, __half* __restrict__ Of,
              const float* __restrict__ query, const float* __restrict__ ref,
              __half* __restrict__ aq, __half* __restrict__ ak) {
    const int bid = blockIdx.x;
    if (bid == 0 && threadIdx.x < MTILES) g_cnt[threadIdx.x] = 0;
    if (bid < 4096) {
        const int z = bid >> 10, r = bid & 1023;
        const int nt = r & 31, kt = r >> 5;
        if (z == 3 && nt >= 4) return;
        const float* W;
        int ldw, nvalid;
        if (z == 0)      { W = Wq;   ldw = CC;     nvalid = CC; }
        else if (z == 1) { W = Wkv;  ldw = 2 * CC; nvalid = CC; }
        else if (z == 2) { W = Wout; ldw = CC;     nvalid = CC; }
        else             { W = Woff; ldw = 128;    nvalid = 128; }

        __shared__ float t[32][33];
        const int tx = threadIdx.x & 31, ty = threadIdx.x >> 5;
        const int n0 = nt * 32, k0 = kt * 32;
#pragma unroll
        for (int j = ty; j < 32; j += 8) {
            int n = n0 + tx, k = k0 + j;
            t[j][tx] = (n < nvalid) ? W[(size_t)k * ldw + n] : 0.0f;
        }
        __syncthreads();
#pragma unroll
        for (int j = ty; j < 32; j += 8) {
            int n = n0 + j, k = k0 + tx;
            float v = t[tx][j];
            __half h = __float2half(v);
            if (z == 0)      { Oq[(size_t)n * K1 + k] = h; }
            else if (z == 1) { Ok[(size_t)n * K1 + k] = h; }
            else if (z == 2) { Oo[(size_t)n * K1 + k] = h; }
            else             { __half l = __float2half(v - __half2float(h));
                               __half* row = Of + (size_t)n * K3;
                               row[k] = h; row[k + 1024] = h; row[k + 2048] = l; }
        }
    } else {
        const int j = bid - 4096;
        const bool isq = j < ACT_BLKS;
        const int blk = isq ? j : j - ACT_BLKS;
        size_t i = (size_t)blk * 256 + threadIdx.x;
        if (i >= (size_t)MM * 128) return;
        size_t rrow = i >> 7;
        int c8 = (int)(i & 127) * 8;
        const float* A = isq ? query : ref;
        const float4* p = reinterpret_cast<const float4*>(A + rrow * CC + c8);
        float4 v0 = p[0], v1 = p[1];
        float vv[8] = {v0.x, v0.y, v0.z, v0.w, v1.x, v1.y, v1.z, v1.w};
        __half hi[8], lo[8];
#pragma unroll
        for (int jj = 0; jj < 8; jj++) {
            hi[jj] = __float2half(vv[jj]);
            lo[jj] = __float2half(vv[jj] - __half2float(hi[jj]));
        }
        if (isq) {
            __half* rp = aq + rrow * K2;
            *reinterpret_cast<uint4*>(rp + c8)        = *reinterpret_cast<uint4*>(hi);
            *reinterpret_cast<uint4*>(rp + c8 + 1024) = *reinterpret_cast<uint4*>(lo);
        } else {
            __half* rp = ak + rrow * K1;
            *reinterpret_cast<uint4*>(rp + c8) = *reinterpret_cast<uint4*>(hi);
        }
    }
}

// ---------------------------------------------------------------------------
// Sampling body (R13-proven): 2 heads/warp, 16 lanes/head, 8 ch/lane.
// ---------------------------------------------------------------------------
__device__ __forceinline__
void sample_body(const __half* __restrict__ q, const __half* __restrict__ k,
                 const float* __restrict__ off, __half* __restrict__ outop) {
    const int warp = (blockIdx.x << 3) + (threadIdx.x >> 5);
    const int lane = threadIdx.x & 31;
    const int grp = lane >> 4;
    const int l16 = lane & 15;
    const int id = warp * 2 + grp;   // always < MM*NHEADS (exact grid fit)

    const int h = id & (NHEADS - 1);
    const int m = id >> 3;
    const int n = m % NN;
    const int b = m / NN;

    const int ch = h * HD + l16 * 8;
    const __half2* qp = reinterpret_cast<const __half2*>(q + (size_t)m * CC + ch);
    float2 qv[4];
#pragma unroll
    for (int j = 0; j < 4; j++) qv[j] = __half22float2(qp[j]);

    const int iy_n = n / WW;
    const int ix_n = n % WW;
    const float cy = -1.0f + 2.0f * (float)iy_n / (float)(HH - 1);
    const float cx = -1.0f + 2.0f * (float)ix_n / (float)(WW - 1);

    const float4* offv = reinterpret_cast<const float4*>(off + (size_t)m * 128 + h * (NPTS * 2));
    float4 o0 = offv[0], o1 = offv[1], o2 = offv[2], o3 = offv[3];
    float offr[16] = {o0.x, o0.y, o0.z, o0.w, o1.x, o1.y, o1.z, o1.w,
                      o2.x, o2.y, o2.z, o2.w, o3.x, o3.y, o3.z, o3.w};

    const __half* kb = k + (size_t)b * NN * CC;

    float sk[NPTS][8];
    float score[NPTS];
    const float scale = 0.08838834764831845f;

#pragma unroll
    for (int p = 0; p < NPTS; p++) {
        float l0 = cy + offr[2 * p + 0];
        float l1 = cx + offr[2 * p + 1];
        float ix = (l0 + 1.0f) * 0.5f * (float)(WW - 1);
        float iy = (l1 + 1.0f) * 0.5f * (float)(HH - 1);
        ix = fminf(fmaxf(ix, 0.0f), (float)(WW - 1));
        iy = fminf(fmaxf(iy, 0.0f), (float)(HH - 1));
        float x0f = floorf(ix), y0f = floorf(iy);
        float wx = ix - x0f, wy = iy - y0f;
        int x0 = (int)x0f, y0 = (int)y0f;
        int x1 = min(x0 + 1, WW - 1);
        int y1 = min(y0 + 1, HH - 1);

        uint4 r00 = *reinterpret_cast<const uint4*>(kb + (size_t)(y0 * WW + x0) * CC + ch);
        uint4 r01 = *reinterpret_cast<const uint4*>(kb + (size_t)(y0 * WW + x1) * CC + ch);
        uint4 r10 = *reinterpret_cast<const uint4*>(kb + (size_t)(y1 * WW + x0) * CC + ch);
        uint4 r11 = *reinterpret_cast<const uint4*>(kb + (size_t)(y1 * WW + x1) * CC + ch);
        const __half2* h00 = reinterpret_cast<const __half2*>(&r00);
        const __half2* h01 = reinterpret_cast<const __half2*>(&r01);
        const __half2* h10 = reinterpret_cast<const __half2*>(&r10);
        const __half2* h11 = reinterpret_cast<const __half2*>(&r11);

        float w00 = (1.0f - wy) * (1.0f - wx);
        float w01 = (1.0f - wy) * wx;
        float w10 = wy * (1.0f - wx);
        float w11 = wy * wx;

        float s = 0.0f;
#pragma unroll
        for (int j = 0; j < 4; j++) {
            float2 a = __half22float2(h00[j]);
            float2 c2 = __half22float2(h01[j]);
            float2 d2 = __half22float2(h10[j]);
            float2 e2 = __half22float2(h11[j]);
            float v0 = a.x * w00 + c2.x * w01 + d2.x * w10 + e2.x * w11;
            float v1 = a.y * w00 + c2.y * w01 + d2.y * w10 + e2.y * w11;
            sk[p][2 * j]     = v0;
            sk[p][2 * j + 1] = v1;
            s += qv[j].x * v0 + qv[j].y * v1;
        }
#pragma unroll
        for (int d = 8; d > 0; d >>= 1)
            s += __shfl_xor_sync(0xFFFFFFFFu, s, d);
        score[p] = s * scale;
    }

    float mx = score[0];
#pragma unroll
    for (int p = 1; p < NPTS; p++) mx = fmaxf(mx, score[p]);
    float denom = 0.0f;
    float e[NPTS];
#pragma unroll
    for (int p = 0; p < NPTS; p++) { e[p] = __expf(score[p] - mx); denom += e[p]; }
    float inv = 1.0f / denom;

    float av[8] = {0.f, 0.f, 0.f, 0.f, 0.f, 0.f, 0.f, 0.f};
#pragma unroll
    for (int p = 0; p < NPTS; p++) {
        float a = e[p] * inv;
#pragma unroll
        for (int j = 0; j < 8; j++) av[j] += a * sk[p][j];
    }

    __half hi[8];
#pragma unroll
    for (int j = 0; j < 8; j++) hi[j] = __float2half(av[j]);
    __half* rp = outop + (size_t)m * K1 + ch;
    *reinterpret_cast<uint4*>(rp) = *reinterpret_cast<uint4*>(hi);
}

// ---------------------------------------------------------------------------
// FUSED sampling + out-GEMM. Blocks [0, SAMP_BLOCKS): sampling (announce
// per-mtile completion). Blocks [SAMP_BLOCKS, +GEMM_BLOCKS): out-GEMM tile,
// spin-waits until its 128 attn rows are produced. Deadlock-free: blocks
// start in index order, gemm blocks come last. cp.async.cg reads L2 directly,
// so producer __threadfence + counter acquire gives coherent attn data.
// ---------------------------------------------------------------------------
__global__ __launch_bounds__(256)
void sample_gemm_fused(const __half* __restrict__ q, const __half* __restrict__ k,
                       const float* __restrict__ off, __half* __restrict__ attnop,
                       const __half* __restrict__ Bo, const float* __restrict__ bout,
                       float* __restrict__ C) {
    extern __shared__ char smem[];
    if (blockIdx.x < SAMP_BLOCKS) {
        sample_body(q, k, off, attnop);
        __syncthreads();
        if (threadIdx.x == 0) {
            __threadfence();
            atomicAdd(&g_cnt[blockIdx.x >> 6], 1);
        }
    } else {
        const int g = blockIdx.x - SAMP_BLOCKS;
        const int mt = g >> 3;          // mt-major: early gemm blocks need early tiles
        const int col = g & 7;
        const int expected = (mt == MTILES - 1) ? 36 : 64;  // tile 85 covers 72 rows
        if (threadIdx.x == 0) {
            while (*(volatile int*)&g_cnt[mt] < expected) __nanosleep(64);
        }
        __syncthreads();
        gemm_body<float>(attnop, K1, Bo, K1, bout, C, CC, mt * 128, col * 128,
                         NCK1, 9999, smem);
    }
}

// ---------------------------------------------------------------------------
extern "C" void kernel_launch(void* const* d_in, const int* in_sizes, int n_in,
                              void* d_out, int out_size) {
    const float* query = (const float*)d_in[0];
    const float* ref   = (const float*)d_in[1];
    const float* Wq    = (const float*)d_in[2];
    const float* bq    = (const float*)d_in[3];
    const float* Wkv   = (const float*)d_in[4];
    const float* bkv   = (const float*)d_in[5];
    const float* Woff  = (const float*)d_in[6];
    const float* boff  = (const float*)d_in[7];
    const float* Wout  = (const float*)d_in[8];
    const float* bout  = (const float*)d_in[9];
    float* outp = (float*)d_out;

    __half *aq, *ak, *bq_op, *bk_op, *bo_op, *bf_op, *qb, *kb;
    float *offp;
    cudaGetSymbolAddress((void**)&aq,    g_aq);
    cudaGetSymbolAddress((void**)&ak,    g_ak);
    cudaGetSymbolAddress((void**)&bq_op, g_bop_q);
    cudaGetSymbolAddress((void**)&bk_op, g_bop_k);
    cudaGetSymbolAddress((void**)&bo_op, g_bop_o);
    cudaGetSymbolAddress((void**)&bf_op, g_bop_f);
    cudaGetSymbolAddress((void**)&qb,    g_q);
    cudaGetSymbolAddress((void**)&kb,    g_k);
    cudaGetSymbolAddress((void**)&offp,  g_offp);

    cudaFuncSetAttribute(gemm3, cudaFuncAttributeMaxDynamicSharedMemorySize, SMEM_SZ);
    cudaFuncSetAttribute(sample_gemm_fused, cudaFuncAttributeMaxDynamicSharedMemorySize, SMEM_SZ);

    // 1. ALL conversions + counter zeroing in one launch
    conv_all<<<4096 + 2 * ACT_BLKS, 256>>>(Wq, Wkv, Wout, Woff,
                                           bq_op, bk_op, bo_op, bf_op,
                                           query, ref, aq, ak);

    // 2. off (K3, A aliased) + q (K1) + k (K1) in one launch, 128-row tiles
    gemm3<<<17 * MTILES, 256, SMEM_SZ>>>(aq, ak, bq_op, bk_op, bf_op,
                                         bq, bkv, boff, qb, kb, offp);

    // 3. fused sampling + out-GEMM (overlapped via per-tile counters)
    sample_gemm_fused<<<SAMP_BLOCKS + GEMM_BLOCKS, 256, SMEM_SZ>>>(
        qb, kb, offp, ak, bo_op, bout, outp);
}

// round 15
// speedup vs baseline: 1.0128x; 1.0128x over previous
#include <cuda_runtime.h>
#include <cuda_fp16.h>
#include <math.h>
#include <cstdint>

// Problem constants
#define BB 8
#define HH 37
#define WW 37
#define NN (HH * WW)          // 1369
#define CC 1024
#define MM (BB * NN)          // 10952
#define NHEADS 8
#define HD 128
#define NPTS 8
#define K1 1024               // 1-term fp16 (q, k, out GEMMs)
#define K2 2048               // [Ah|Al] activation layout (off GEMM aliases term2 -> term0)
#define K3 3072               // off GEMM logical K (B = [Bh|Bh|Bl])
#define NCK1 (K1 / 64)        // 16
#define NCK3 (K3 / 64)        // 48
#define STAGES 3
#define STAGE_BYTES 32768     // A 16K + B 16K
#define SMEM_SZ (STAGES * STAGE_BYTES)   // 96KB -> 2 CTAs/SM
#define MTILES 86             // ceil(MM/128)
#define ACT_BLKS 5476         // MM*128/256

// ---------------------------------------------------------------------------
// Scratch
// ---------------------------------------------------------------------------
__device__ __half g_aq[MM * K2];      // query [Ah|Al] (q uses K1 prefix, off aliases chunks)
__device__ __half g_ak[MM * K1];      // ref [Ah]; reused as attn [Ah]
__device__ __half g_bop_q[CC * K1];   // Wq [Bh]
__device__ __half g_bop_k[CC * K1];   // Wkv[:, :C] [Bh]
__device__ __half g_bop_o[CC * K1];   // Wout [Bh]
__device__ __half g_bop_f[128 * K3];  // Woff [Bh|Bh|Bl]
__device__ __half g_q[MM * CC];       // q in fp16
__device__ __half g_k[MM * CC];       // k in fp16
__device__ float  g_offp[MM * 128];

// ---------------------------------------------------------------------------
__device__ __forceinline__ uint32_t smem_u32(const void* p) {
    uint32_t a;
    asm("{ .reg .u64 t; cvta.to.shared.u64 t, %1; cvt.u32.u64 %0, t; }" : "=r"(a) : "l"(p));
    return a;
}
__device__ __forceinline__ void cp16(uint32_t dst, const void* src, bool valid) {
    int sz = valid ? 16 : 0;
    asm volatile("cp.async.cg.shared.global [%0], [%1], 16, %2;"
                 :: "r"(dst), "l"(src), "r"(sz) : "memory");
}
#define CP_COMMIT() asm volatile("cp.async.commit_group;" ::: "memory")
#define CP_WAIT1()  asm volatile("cp.async.wait_group 1;" ::: "memory")

__device__ __forceinline__ void ldsm4(uint32_t* r, uint32_t addr) {
    asm volatile("ldmatrix.sync.aligned.m8n8.x4.shared.b16 {%0,%1,%2,%3}, [%4];"
                 : "=r"(r[0]), "=r"(r[1]), "=r"(r[2]), "=r"(r[3]) : "r"(addr));
}
__device__ __forceinline__ void mma16816(float* c, const uint32_t* a, const uint32_t* b) {
    asm volatile(
        "mma.sync.aligned.m16n8k16.row.col.f32.f16.f16.f32 "
        "{%0,%1,%2,%3},{%4,%5,%6,%7},{%8,%9},{%0,%1,%2,%3};"
        : "+f"(c[0]), "+f"(c[1]), "+f"(c[2]), "+f"(c[3])
        : "r"(a[0]), "r"(a[1]), "r"(a[2]), "r"(a[3]), "r"(b[0]), "r"(b[1]));
}

// ---------------------------------------------------------------------------
// GEMM body: CTA 128x128, 4 warps (2m x 2n), warp tile 64x64 (CUTLASS-style),
// 128 threads, 3-stage cp.async, ONE sync per chunk. ka_wrap: A-chunk alias.
// ---------------------------------------------------------------------------
template <typename OutT>
__device__ __forceinline__
void gemm_body(const __half* __restrict__ A, int lda,
               const __half* __restrict__ B, int ldb,
               const float* __restrict__ bias, OutT* __restrict__ C,
               int ldc, int m0, int col0, int nchunk, int ka_wrap, char* smem) {
    const uint32_t sb0 = smem_u32(smem);
    const int tid = threadIdx.x, wid = tid >> 5, lane = tid & 31;
    const __half* Bc0 = B + (size_t)col0 * ldb;

    auto load_stage = [&](int ck, int stage) {
        const uint32_t sa = sb0 + stage * STAGE_BYTES;
        const int ca = (ck >= ka_wrap) ? ck - ka_wrap : ck;
        const __half* Ac = A + ca * 64;
        const __half* Bc = Bc0 + ck * 64;
#pragma unroll
        for (int i = 0; i < 8; i++) {
            int id = tid + i * 128;
            int row = id >> 3, c16 = id & 7;
            int gr = m0 + row;
            bool v = gr < MM;
            int grc = v ? gr : (MM - 1);
            uint32_t dst = sa + row * 128 + (((uint32_t)c16 ^ (row & 7)) << 4);
            cp16(dst, Ac + (size_t)grc * lda + c16 * 8, v);
        }
#pragma unroll
        for (int i = 0; i < 8; i++) {
            int id = tid + i * 128;
            int row = id >> 3, c16 = id & 7;
            uint32_t dst = sa + 16384 + row * 128 + (((uint32_t)c16 ^ (row & 7)) << 4);
            cp16(dst, Bc + (size_t)row * ldb + c16 * 8, true);
        }
        CP_COMMIT();
    };

    float acc[4][8][4];
#pragma unroll
    for (int mt = 0; mt < 4; mt++)
#pragma unroll
        for (int nt = 0; nt < 8; nt++)
#pragma unroll
            for (int j = 0; j < 4; j++) acc[mt][nt][j] = 0.0f;

    load_stage(0, 0);
    load_stage(1, 1);

    const int wm = (wid & 1) * 64;
    const int wn = (wid >> 1) * 64;

    for (int c = 0; c < nchunk; c++) {
        CP_WAIT1();
        __syncthreads();   // single barrier; also protects buffer reuse
        if (c + 2 < nchunk) load_stage(c + 2, (c + 2) % STAGES);
        else CP_COMMIT();

        const uint32_t sa = sb0 + (c % STAGES) * STAGE_BYTES;
        const uint32_t sbB = sa + 16384;

#pragma unroll
        for (int ks = 0; ks < 4; ks++) {
            uint32_t af[4][4];
#pragma unroll
            for (int mt = 0; mt < 4; mt++) {
                int row = wm + mt * 16 + (lane & 15);
                uint32_t c16 = (uint32_t)(ks * 2 + (lane >> 4)) ^ (row & 7);
                ldsm4(af[mt], sa + row * 128 + (c16 << 4));
            }
            uint32_t bf[8][2];
#pragma unroll
            for (int nt2 = 0; nt2 < 4; nt2++) {
                int group = lane >> 3;
                int nrow = wn + nt2 * 16 + (group >> 1) * 8 + (lane & 7);
                uint32_t c16 = (uint32_t)(ks * 2 + (group & 1)) ^ (nrow & 7);
                uint32_t r[4];
                ldsm4(r, sbB + nrow * 128 + (c16 << 4));
                bf[nt2 * 2][0] = r[0]; bf[nt2 * 2][1] = r[1];
                bf[nt2 * 2 + 1][0] = r[2]; bf[nt2 * 2 + 1][1] = r[3];
            }
#pragma unroll
            for (int mt = 0; mt < 4; mt++)
#pragma unroll
                for (int nt = 0; nt < 8; nt++)
                    mma16816(acc[mt][nt], af[mt], bf[nt]);
        }
    }
    __syncthreads();

    const int lr = lane >> 2, lc = (lane & 3) * 2;
#pragma unroll
    for (int mt = 0; mt < 4; mt++) {
#pragma unroll
        for (int nt = 0; nt < 8; nt++) {
            int r0 = m0 + wm + mt * 16 + lr;
            int cb = col0 + wn + nt * 8 + lc;
            float b0 = bias[cb], b1 = bias[cb + 1];
            if (r0 < MM) {
                if (sizeof(OutT) == 2) {
                    __half2 v = __floats2half2_rn(acc[mt][nt][0] + b0, acc[mt][nt][1] + b1);
                    *reinterpret_cast<__half2*>((__half*)C + (size_t)r0 * ldc + cb) = v;
                } else {
                    float2 v = make_float2(acc[mt][nt][0] + b0, acc[mt][nt][1] + b1);
                    *reinterpret_cast<float2*>((float*)C + (size_t)r0 * ldc + cb) = v;
                }
            }
            int r1 = r0 + 8;
            if (r1 < MM) {
                if (sizeof(OutT) == 2) {
                    __half2 v = __floats2half2_rn(acc[mt][nt][2] + b0, acc[mt][nt][3] + b1);
                    *reinterpret_cast<__half2*>((__half*)C + (size_t)r1 * ldc + cb) = v;
                } else {
                    float2 v = make_float2(acc[mt][nt][2] + b0, acc[mt][nt][3] + b1);
                    *reinterpret_cast<float2*>((float*)C + (size_t)r1 * ldc + cb) = v;
                }
            }
        }
    }
}

// Merged off + q + k GEMM. t = bx / MTILES:
// t == 0: off (K3 logical, A aliased mod 32); t in [1,9): q; t in [9,17): k.
__global__ __launch_bounds__(128)
void gemm3(const __half* __restrict__ Aq, const __half* __restrict__ Ak,
           const __half* __restrict__ Bq, const __half* __restrict__ Bk,
           const __half* __restrict__ Bf,
           const float* __restrict__ bq, const float* __restrict__ bkv,
           const float* __restrict__ boff,
           __half* __restrict__ Cq, __half* __restrict__ Ck, float* __restrict__ Coff) {
    extern __shared__ char smem[];
    const int bx = blockIdx.x;
    const int t = bx / MTILES;
    const int m0 = (bx % MTILES) * 128;
    if (t == 0) {
        gemm_body<float>(Aq, K2, Bf, K3, boff, Coff, 128, m0, 0, NCK3, 32, smem);
    } else if (t < 9) {
        gemm_body<__half>(Aq, K2, Bq, K1, bq, Cq, CC, m0, (t - 1) * 128, NCK1, 9999, smem);
    } else {
        gemm_body<__half>(Ak, K1, Bk, K1, bkv, Ck, CC, m0, (t - 9) * 128, NCK1, 9999, smem);
    }
}

// Final GEMM: out = attn(K1) @ Wout + bout
__global__ __launch_bounds__(128)
void gemm_out(const __half* __restrict__ A, const __half* __restrict__ B,
              const float* __restrict__ bias, float* __restrict__ C) {
    extern __shared__ char smem[];
    gemm_body<float>(A, K1, B, K1, bias, C, CC, blockIdx.y * 128, blockIdx.x * 128,
                     NCK1, 9999, smem);
}

// ---------------------------------------------------------------------------
// ALL conversions in one launch. Grid = 4096 (weights) + 2*ACT_BLKS (acts).
// ---------------------------------------------------------------------------
__global__ __launch_bounds__(256)
void conv_all(const float* __restrict__ Wq, const float* __restrict__ Wkv,
              const float* __restrict__ Wout, const float* __restrict__ Woff,
              __half* __restrict__ Oq, __half* __restrict__ Ok,
              __half* __restrict__ Oo, __half* __restrict__ Of,
              const float* __restrict__ query, const float* __restrict__ ref,
              __half* __restrict__ aq, __half* __restrict__ ak) {
    const int bid = blockIdx.x;
    if (bid < 4096) {
        const int z = bid >> 10, r = bid & 1023;
        const int nt = r & 31, kt = r >> 5;
        if (z == 3 && nt >= 4) return;
        const float* W;
        int ldw, nvalid;
        if (z == 0)      { W = Wq;   ldw = CC;     nvalid = CC; }
        else if (z == 1) { W = Wkv;  ldw = 2 * CC; nvalid = CC; }
        else if (z == 2) { W = Wout; ldw = CC;     nvalid = CC; }
        else             { W = Woff; ldw = 128;    nvalid = 128; }

        __shared__ float t[32][33];
        const int tx = threadIdx.x & 31, ty = threadIdx.x >> 5;
        const int n0 = nt * 32, k0 = kt * 32;
#pragma unroll
        for (int j = ty; j < 32; j += 8) {
            int n = n0 + tx, k = k0 + j;
            t[j][tx] = (n < nvalid) ? W[(size_t)k * ldw + n] : 0.0f;
        }
        __syncthreads();
#pragma unroll
        for (int j = ty; j < 32; j += 8) {
            int n = n0 + j, k = k0 + tx;
            float v = t[tx][j];
            __half h = __float2half(v);
            if (z == 0)      { Oq[(size_t)n * K1 + k] = h; }
            else if (z == 1) { Ok[(size_t)n * K1 + k] = h; }
            else if (z == 2) { Oo[(size_t)n * K1 + k] = h; }
            else             { __half l = __float2half(v - __half2float(h));
                               __half* row = Of + (size_t)n * K3;
                               row[k] = h; row[k + 1024] = h; row[k + 2048] = l; }
        }
    } else {
        const int j = bid - 4096;
        const bool isq = j < ACT_BLKS;
        const int blk = isq ? j : j - ACT_BLKS;
        size_t i = (size_t)blk * 256 + threadIdx.x;
        if (i >= (size_t)MM * 128) return;
        size_t rrow = i >> 7;
        int c8 = (int)(i & 127) * 8;
        const float* A = isq ? query : ref;
        const float4* p = reinterpret_cast<const float4*>(A + rrow * CC + c8);
        float4 v0 = p[0], v1 = p[1];
        float vv[8] = {v0.x, v0.y, v0.z, v0.w, v1.x, v1.y, v1.z, v1.w};
        __half hi[8], lo[8];
#pragma unroll
        for (int jj = 0; jj < 8; jj++) {
            hi[jj] = __float2half(vv[jj]);
            lo[jj] = __float2half(vv[jj] - __half2float(hi[jj]));
        }
        if (isq) {
            __half* rp = aq + rrow * K2;
            *reinterpret_cast<uint4*>(rp + c8)        = *reinterpret_cast<uint4*>(hi);
            *reinterpret_cast<uint4*>(rp + c8 + 1024) = *reinterpret_cast<uint4*>(lo);
        } else {
            __half* rp = ak + rrow * K1;
            *reinterpret_cast<uint4*>(rp + c8) = *reinterpret_cast<uint4*>(hi);
        }
    }
}

// ---------------------------------------------------------------------------
// Sampling + attention (R13-proven): 2 heads/warp, 16 lanes/head, 8 ch/lane.
// Writes fp16 attn operand [Ah] (stride K1) directly.
// ---------------------------------------------------------------------------
__global__ __launch_bounds__(256)
void sample_attn_kernel(const __half* __restrict__ q, const __half* __restrict__ k,
                        const float* __restrict__ off, __half* __restrict__ outop) {
    const int warp = (blockIdx.x * blockDim.x + threadIdx.x) >> 5;
    const int lane = threadIdx.x & 31;
    const int grp = lane >> 4;
    const int l16 = lane & 15;
    const int id = warp * 2 + grp;
    if (id >= MM * NHEADS) return;

    const int h = id & (NHEADS - 1);
    const int m = id >> 3;
    const int n = m % NN;
    const int b = m / NN;

    const int ch = h * HD + l16 * 8;
    const __half2* qp = reinterpret_cast<const __half2*>(q + (size_t)m * CC + ch);
    float2 qv[4];
#pragma unroll
    for (int j = 0; j < 4; j++) qv[j] = __half22float2(qp[j]);

    const int iy_n = n / WW;
    const int ix_n = n % WW;
    const float cy = -1.0f + 2.0f * (float)iy_n / (float)(HH - 1);
    const float cx = -1.0f + 2.0f * (float)ix_n / (float)(WW - 1);

    const float4* offv = reinterpret_cast<const float4*>(off + (size_t)m * 128 + h * (NPTS * 2));
    float4 o0 = offv[0], o1 = offv[1], o2 = offv[2], o3 = offv[3];
    float offr[16] = {o0.x, o0.y, o0.z, o0.w, o1.x, o1.y, o1.z, o1.w,
                      o2.x, o2.y, o2.z, o2.w, o3.x, o3.y, o3.z, o3.w};

    const __half* kb = k + (size_t)b * NN * CC;

    float sk[NPTS][8];
    float score[NPTS];
    const float scale = 0.08838834764831845f;

#pragma unroll
    for (int p = 0; p < NPTS; p++) {
        float l0 = cy + offr[2 * p + 0];
        float l1 = cx + offr[2 * p + 1];
        float ix = (l0 + 1.0f) * 0.5f * (float)(WW - 1);
        float iy = (l1 + 1.0f) * 0.5f * (float)(HH - 1);
        ix = fminf(fmaxf(ix, 0.0f), (float)(WW - 1));
        iy = fminf(fmaxf(iy, 0.0f), (float)(HH - 1));
        float x0f = floorf(ix), y0f = floorf(iy);
        float wx = ix - x0f, wy = iy - y0f;
        int x0 = (int)x0f, y0 = (int)y0f;
        int x1 = min(x0 + 1, WW - 1);
        int y1 = min(y0 + 1, HH - 1);

        uint4 r00 = *reinterpret_cast<const uint4*>(kb + (size_t)(y0 * WW + x0) * CC + ch);
        uint4 r01 = *reinterpret_cast<const uint4*>(kb + (size_t)(y0 * WW + x1) * CC + ch);
        uint4 r10 = *reinterpret_cast<const uint4*>(kb + (size_t)(y1 * WW + x0) * CC + ch);
        uint4 r11 = *reinterpret_cast<const uint4*>(kb + (size_t)(y1 * WW + x1) * CC + ch);
        const __half2* h00 = reinterpret_cast<const __half2*>(&r00);
        const __half2* h01 = reinterpret_cast<const __half2*>(&r01);
        const __half2* h10 = reinterpret_cast<const __half2*>(&r10);
        const __half2* h11 = reinterpret_cast<const __half2*>(&r11);

        float w00 = (1.0f - wy) * (1.0f - wx);
        float w01 = (1.0f - wy) * wx;
        float w10 = wy * (1.0f - wx);
        float w11 = wy * wx;

        float s = 0.0f;
#pragma unroll
        for (int j = 0; j < 4; j++) {
            float2 a = __half22float2(h00[j]);
            float2 c2 = __half22float2(h01[j]);
            float2 d2 = __half22float2(h10[j]);
            float2 e2 = __half22float2(h11[j]);
            float v0 = a.x * w00 + c2.x * w01 + d2.x * w10 + e2.x * w11;
            float v1 = a.y * w00 + c2.y * w01 + d2.y * w10 + e2.y * w11;
            sk[p][2 * j]     = v0;
            sk[p][2 * j + 1] = v1;
            s += qv[j].x * v0 + qv[j].y * v1;
        }
#pragma unroll
        for (int d = 8; d > 0; d >>= 1)
            s += __shfl_xor_sync(0xFFFFFFFFu, s, d);
        score[p] = s * scale;
    }

    float mx = score[0];
#pragma unroll
    for (int p = 1; p < NPTS; p++) mx = fmaxf(mx, score[p]);
    float denom = 0.0f;
    float e[NPTS];
#pragma unroll
    for (int p = 0; p < NPTS; p++) { e[p] = __expf(score[p] - mx); denom += e[p]; }
    float inv = 1.0f / denom;

    float av[8] = {0.f, 0.f, 0.f, 0.f, 0.f, 0.f, 0.f, 0.f};
#pragma unroll
    for (int p = 0; p < NPTS; p++) {
        float a = e[p] * inv;
#pragma unroll
        for (int j = 0; j < 8; j++) av[j] += a * sk[p][j];
    }

    __half hi[8];
#pragma unroll
    for (int j = 0; j < 8; j++) hi[j] = __float2half(av[j]);
    __half* rp = outop + (size_t)m * K1 + ch;
    *reinterpret_cast<uint4*>(rp) = *reinterpret_cast<uint4*>(hi);
}

// ---------------------------------------------------------------------------
extern "C" void kernel_launch(void* const* d_in, const int* in_sizes, int n_in,
                              void* d_out, int out_size) {
    const float* query = (const float*)d_in[0];
    const float* ref   = (const float*)d_in[1];
    const float* Wq    = (const float*)d_in[2];
    const float* bq    = (const float*)d_in[3];
    const float* Wkv   = (const float*)d_in[4];
    const float* bkv   = (const float*)d_in[5];
    const float* Woff  = (const float*)d_in[6];
    const float* boff  = (const float*)d_in[7];
    const float* Wout  = (const float*)d_in[8];
    const float* bout  = (const float*)d_in[9];
    float* outp = (float*)d_out;

    __half *aq, *ak, *bq_op, *bk_op, *bo_op, *bf_op, *qb, *kb;
    float *offp;
    cudaGetSymbolAddress((void**)&aq,    g_aq);
    cudaGetSymbolAddress((void**)&ak,    g_ak);
    cudaGetSymbolAddress((void**)&bq_op, g_bop_q);
    cudaGetSymbolAddress((void**)&bk_op, g_bop_k);
    cudaGetSymbolAddress((void**)&bo_op, g_bop_o);
    cudaGetSymbolAddress((void**)&bf_op, g_bop_f);
    cudaGetSymbolAddress((void**)&qb,    g_q);
    cudaGetSymbolAddress((void**)&kb,    g_k);
    cudaGetSymbolAddress((void**)&offp,  g_offp);

    cudaFuncSetAttribute(gemm3, cudaFuncAttributeMaxDynamicSharedMemorySize, SMEM_SZ);
    cudaFuncSetAttribute(gemm_out, cudaFuncAttributeMaxDynamicSharedMemorySize, SMEM_SZ);

    // 1. ALL conversions (weights + both activations) in one launch
    conv_all<<<4096 + 2 * ACT_BLKS, 256>>>(Wq, Wkv, Wout, Woff,
                                           bq_op, bk_op, bo_op, bf_op,
                                           query, ref, aq, ak);

    // 2. off (K3, A aliased) + q (K1) + k (K1) in one launch, 64x64 warp tiles
    gemm3<<<17 * MTILES, 128, SMEM_SZ>>>(aq, ak, bq_op, bk_op, bf_op,
                                         bq, bkv, boff, qb, kb, offp);

    // 3. sampling + attention; 2 heads/warp; writes fp16 [Ah] operand into ak
    {
        int warps = (MM * NHEADS + 1) / 2;          // 43808
        int blocks = (warps * 32 + 255) / 256;      // 5476
        sample_attn_kernel<<<blocks, 256>>>(qb, kb, offp, ak);
    }

    // 4. out = attn @ Wout + bout  (K1), 64x64 warp tiles
    gemm_out<<<dim3(8, MTILES), 128, SMEM_SZ>>>(ak, bo_op, bout, outp);
}

// round 16
// speedup vs baseline: 1.0142x; 1.0014x over previous
#include <cuda_runtime.h>
#include <cuda_fp16.h>
#include <math.h>
#include <cstdint>

// Problem constants
#define BB 8
#define HH 37
#define WW 37
#define NN (HH * WW)          // 1369
#define CC 1024
#define MM (BB * NN)          // 10952
#define NHEADS 8
#define HD 128
#define NPTS 8
#define K1 1024               // 1-term fp16 (q, k, out GEMMs)
#define K2 2048               // [Ah|Al] activation layout (off GEMM aliases term2 -> term0)
#define K3 3072               // off GEMM logical K (B = [Bh|Bh|Bl])
#define NCK1 (K1 / 64)        // 16
#define NCK3 (K3 / 64)        // 48
#define STAGES 3
#define STAGE_BYTES 32768     // A 16K + B 16K
#define SMEM_SZ (STAGES * STAGE_BYTES)   // 96KB -> 2 CTAs/SM (proven best)
#define MTILES 86             // ceil(MM/128)
#define ACT_BLKS 5476         // MM*128/256

// PDL primitives (sm_90+)
#define GDC_WAIT()   asm volatile("griddepcontrol.wait;" ::: "memory")
#define GDC_LAUNCH() asm volatile("griddepcontrol.launch_dependents;" ::: "memory")

// ---------------------------------------------------------------------------
// Scratch
// ---------------------------------------------------------------------------
__device__ __half g_aq[MM * K2];      // query [Ah|Al] (q uses K1 prefix, off aliases chunks)
__device__ __half g_ak[MM * K1];      // ref [Ah]; reused as attn [Ah]
__device__ __half g_bop_q[CC * K1];   // Wq [Bh]
__device__ __half g_bop_k[CC * K1];   // Wkv[:, :C] [Bh]
__device__ __half g_bop_o[CC * K1];   // Wout [Bh]
__device__ __half g_bop_f[128 * K3];  // Woff [Bh|Bh|Bl]
__device__ __half g_q[MM * CC];       // q in fp16
__device__ __half g_k[MM * CC];       // k in fp16
__device__ float  g_offp[MM * 128];

// ---------------------------------------------------------------------------
__device__ __forceinline__ uint32_t smem_u32(const void* p) {
    uint32_t a;
    asm("{ .reg .u64 t; cvta.to.shared.u64 t, %1; cvt.u32.u64 %0, t; }" : "=r"(a) : "l"(p));
    return a;
}
__device__ __forceinline__ void cp16(uint32_t dst, const void* src, bool valid) {
    int sz = valid ? 16 : 0;
    asm volatile("cp.async.cg.shared.global [%0], [%1], 16, %2;"
                 :: "r"(dst), "l"(src), "r"(sz) : "memory");
}
#define CP_COMMIT() asm volatile("cp.async.commit_group;" ::: "memory")
#define CP_WAIT1()  asm volatile("cp.async.wait_group 1;" ::: "memory")

__device__ __forceinline__ void ldsm4(uint32_t* r, uint32_t addr) {
    asm volatile("ldmatrix.sync.aligned.m8n8.x4.shared.b16 {%0,%1,%2,%3}, [%4];"
                 : "=r"(r[0]), "=r"(r[1]), "=r"(r[2]), "=r"(r[3]) : "r"(addr));
}
__device__ __forceinline__ void mma16816(float* c, const uint32_t* a, const uint32_t* b) {
    asm volatile(
        "mma.sync.aligned.m16n8k16.row.col.f32.f16.f16.f32 "
        "{%0,%1,%2,%3},{%4,%5,%6,%7},{%8,%9},{%0,%1,%2,%3};"
        : "+f"(c[0]), "+f"(c[1]), "+f"(c[2]), "+f"(c[3])
        : "r"(a[0]), "r"(a[1]), "r"(a[2]), "r"(a[3]), "r"(b[0]), "r"(b[1]));
}

// ---------------------------------------------------------------------------
// GEMM body (R13-proven): CTA 128x128, 8 warps 64x32, 3-stage cp.async,
// ONE sync per chunk. ka_wrap: A-chunk aliasing (off GEMM term2 -> term0).
// ---------------------------------------------------------------------------
template <typename OutT>
__device__ __forceinline__
void gemm_body(const __half* __restrict__ A, int lda,
               const __half* __restrict__ B, int ldb,
               const float* __restrict__ bias, OutT* __restrict__ C,
               int ldc, int m0, int col0, int nchunk, int ka_wrap, char* smem) {
    const uint32_t sb0 = smem_u32(smem);
    const int tid = threadIdx.x, wid = tid >> 5, lane = tid & 31;
    const __half* Bc0 = B + (size_t)col0 * ldb;

    auto load_stage = [&](int ck, int stage) {
        const uint32_t sa = sb0 + stage * STAGE_BYTES;
        const int ca = (ck >= ka_wrap) ? ck - ka_wrap : ck;
        const __half* Ac = A + ca * 64;
        const __half* Bc = Bc0 + ck * 64;
#pragma unroll
        for (int i = 0; i < 4; i++) {
            int id = tid + i * 256;
            int row = id >> 3, c16 = id & 7;
            int gr = m0 + row;
            bool v = gr < MM;
            int grc = v ? gr : (MM - 1);
            uint32_t dst = sa + row * 128 + (((uint32_t)c16 ^ (row & 7)) << 4);
            cp16(dst, Ac + (size_t)grc * lda + c16 * 8, v);
        }
#pragma unroll
        for (int i = 0; i < 4; i++) {
            int id = tid + i * 256;
            int row = id >> 3, c16 = id & 7;
            uint32_t dst = sa + 16384 + row * 128 + (((uint32_t)c16 ^ (row & 7)) << 4);
            cp16(dst, Bc + (size_t)row * ldb + c16 * 8, true);
        }
        CP_COMMIT();
    };

    float acc[4][4][4];
#pragma unroll
    for (int mt = 0; mt < 4; mt++)
#pragma unroll
        for (int nt = 0; nt < 4; nt++)
#pragma unroll
            for (int j = 0; j < 4; j++) acc[mt][nt][j] = 0.0f;

    load_stage(0, 0);
    load_stage(1, 1);

    const int wm = (wid & 1) * 64;
    const int wn = (wid >> 1) * 32;

    for (int c = 0; c < nchunk; c++) {
        CP_WAIT1();
        __syncthreads();   // single barrier; also protects buffer reuse
        if (c + 2 < nchunk) load_stage(c + 2, (c + 2) % STAGES);
        else CP_COMMIT();

        const uint32_t sa = sb0 + (c % STAGES) * STAGE_BYTES;
        const uint32_t sbB = sa + 16384;

#pragma unroll
        for (int ks = 0; ks < 4; ks++) {
            uint32_t af[4][4];
#pragma unroll
            for (int mt = 0; mt < 4; mt++) {
                int row = wm + mt * 16 + (lane & 15);
                uint32_t c16 = (uint32_t)(ks * 2 + (lane >> 4)) ^ (row & 7);
                ldsm4(af[mt], sa + row * 128 + (c16 << 4));
            }
            uint32_t bf[4][2];
#pragma unroll
            for (int nt2 = 0; nt2 < 2; nt2++) {
                int group = lane >> 3;
                int nrow = wn + nt2 * 16 + (group >> 1) * 8 + (lane & 7);
                uint32_t c16 = (uint32_t)(ks * 2 + (group & 1)) ^ (nrow & 7);
                uint32_t r[4];
                ldsm4(r, sbB + nrow * 128 + (c16 << 4));
                bf[nt2 * 2][0] = r[0]; bf[nt2 * 2][1] = r[1];
                bf[nt2 * 2 + 1][0] = r[2]; bf[nt2 * 2 + 1][1] = r[3];
            }
#pragma unroll
            for (int mt = 0; mt < 4; mt++)
#pragma unroll
                for (int nt = 0; nt < 4; nt++)
                    mma16816(acc[mt][nt], af[mt], bf[nt]);
        }
    }
    __syncthreads();

    const int lr = lane >> 2, lc = (lane & 3) * 2;
#pragma unroll
    for (int mt = 0; mt < 4; mt++) {
#pragma unroll
        for (int nt = 0; nt < 4; nt++) {
            int r0 = m0 + wm + mt * 16 + lr;
            int cb = col0 + wn + nt * 8 + lc;
            float b0 = bias[cb], b1 = bias[cb + 1];
            if (r0 < MM) {
                if (sizeof(OutT) == 2) {
                    __half2 v = __floats2half2_rn(acc[mt][nt][0] + b0, acc[mt][nt][1] + b1);
                    *reinterpret_cast<__half2*>((__half*)C + (size_t)r0 * ldc + cb) = v;
                } else {
                    float2 v = make_float2(acc[mt][nt][0] + b0, acc[mt][nt][1] + b1);
                    *reinterpret_cast<float2*>((float*)C + (size_t)r0 * ldc + cb) = v;
                }
            }
            int r1 = r0 + 8;
            if (r1 < MM) {
                if (sizeof(OutT) == 2) {
                    __half2 v = __floats2half2_rn(acc[mt][nt][2] + b0, acc[mt][nt][3] + b1);
                    *reinterpret_cast<__half2*>((__half*)C + (size_t)r1 * ldc + cb) = v;
                } else {
                    float2 v = make_float2(acc[mt][nt][2] + b0, acc[mt][nt][3] + b1);
                    *reinterpret_cast<float2*>((float*)C + (size_t)r1 * ldc + cb) = v;
                }
            }
        }
    }
}

// Merged off + q + k GEMM. t = bx / MTILES:
// t == 0: off (K3 logical, A aliased mod 32); t in [1,9): q; t in [9,17): k.
__global__ __launch_bounds__(256)
void gemm3(const __half* __restrict__ Aq, const __half* __restrict__ Ak,
           const __half* __restrict__ Bq, const __half* __restrict__ Bk,
           const __half* __restrict__ Bf,
           const float* __restrict__ bq, const float* __restrict__ bkv,
           const float* __restrict__ boff,
           __half* __restrict__ Cq, __half* __restrict__ Ck, float* __restrict__ Coff) {
    extern __shared__ char smem[];
    GDC_WAIT();   // inputs come from conv_all
    const int bx = blockIdx.x;
    const int t = bx / MTILES;
    const int m0 = (bx % MTILES) * 128;
    if (t == 0) {
        gemm_body<float>(Aq, K2, Bf, K3, boff, Coff, 128, m0, 0, NCK3, 32, smem);
    } else if (t < 9) {
        gemm_body<__half>(Aq, K2, Bq, K1, bq, Cq, CC, m0, (t - 1) * 128, NCK1, 9999, smem);
    } else {
        gemm_body<__half>(Ak, K1, Bk, K1, bkv, Ck, CC, m0, (t - 9) * 128, NCK1, 9999, smem);
    }
    GDC_LAUNCH();
}

// Final GEMM: out = attn(K1) @ Wout + bout
__global__ __launch_bounds__(256)
void gemm_out(const __half* __restrict__ A, const __half* __restrict__ B,
              const float* __restrict__ bias, float* __restrict__ C) {
    extern __shared__ char smem[];
    GDC_WAIT();   // attn operand comes from sampling
    gemm_body<float>(A, K1, B, K1, bias, C, CC, blockIdx.y * 128, blockIdx.x * 128,
                     NCK1, 9999, smem);
}

// ---------------------------------------------------------------------------
// ALL conversions in one launch. Grid = 4096 (weights) + 2*ACT_BLKS (acts).
// ---------------------------------------------------------------------------
__global__ __launch_bounds__(256)
void conv_all(const float* __restrict__ Wq, const float* __restrict__ Wkv,
              const float* __restrict__ Wout, const float* __restrict__ Woff,
              __half* __restrict__ Oq, __half* __restrict__ Ok,
              __half* __restrict__ Oo, __half* __restrict__ Of,
              const float* __restrict__ query, const float* __restrict__ ref,
              __half* __restrict__ aq, __half* __restrict__ ak) {
    const int bid = blockIdx.x;
    if (bid < 4096) {
        const int z = bid >> 10, r = bid & 1023;
        const int nt = r & 31, kt = r >> 5;
        if (z == 3 && nt >= 4) { GDC_LAUNCH(); return; }
        const float* W;
        int ldw, nvalid;
        if (z == 0)      { W = Wq;   ldw = CC;     nvalid = CC; }
        else if (z == 1) { W = Wkv;  ldw = 2 * CC; nvalid = CC; }
        else if (z == 2) { W = Wout; ldw = CC;     nvalid = CC; }
        else             { W = Woff; ldw = 128;    nvalid = 128; }

        __shared__ float t[32][33];
        const int tx = threadIdx.x & 31, ty = threadIdx.x >> 5;
        const int n0 = nt * 32, k0 = kt * 32;
#pragma unroll
        for (int j = ty; j < 32; j += 8) {
            int n = n0 + tx, k = k0 + j;
            t[j][tx] = (n < nvalid) ? W[(size_t)k * ldw + n] : 0.0f;
        }
        __syncthreads();
#pragma unroll
        for (int j = ty; j < 32; j += 8) {
            int n = n0 + j, k = k0 + tx;
            float v = t[tx][j];
            __half h = __float2half(v);
            if (z == 0)      { Oq[(size_t)n * K1 + k] = h; }
            else if (z == 1) { Ok[(size_t)n * K1 + k] = h; }
            else if (z == 2) { Oo[(size_t)n * K1 + k] = h; }
            else             { __half l = __float2half(v - __half2float(h));
                               __half* row = Of + (size_t)n * K3;
                               row[k] = h; row[k + 1024] = h; row[k + 2048] = l; }
        }
    } else {
        const int j = bid - 4096;
        const bool isq = j < ACT_BLKS;
        const int blk = isq ? j : j - ACT_BLKS;
        size_t i = (size_t)blk * 256 + threadIdx.x;
        if (i < (size_t)MM * 128) {
            size_t rrow = i >> 7;
            int c8 = (int)(i & 127) * 8;
            const float* A = isq ? query : ref;
            const float4* p = reinterpret_cast<const float4*>(A + rrow * CC + c8);
            float4 v0 = p[0], v1 = p[1];
            float vv[8] = {v0.x, v0.y, v0.z, v0.w, v1.x, v1.y, v1.z, v1.w};
            __half hi[8], lo[8];
#pragma unroll
            for (int jj = 0; jj < 8; jj++) {
                hi[jj] = __float2half(vv[jj]);
                lo[jj] = __float2half(vv[jj] - __half2float(hi[jj]));
            }
            if (isq) {
                __half* rp = aq + rrow * K2;
                *reinterpret_cast<uint4*>(rp + c8)        = *reinterpret_cast<uint4*>(hi);
                *reinterpret_cast<uint4*>(rp + c8 + 1024) = *reinterpret_cast<uint4*>(lo);
            } else {
                __half* rp = ak + rrow * K1;
                *reinterpret_cast<uint4*>(rp + c8) = *reinterpret_cast<uint4*>(hi);
            }
        }
    }
    GDC_LAUNCH();
}

// ---------------------------------------------------------------------------
// Sampling + attention (R13-proven): 2 heads/warp, 16 lanes/head, 8 ch/lane.
// Writes fp16 attn operand [Ah] (stride K1) directly.
// ---------------------------------------------------------------------------
__global__ __launch_bounds__(256)
void sample_attn_kernel(const __half* __restrict__ q, const __half* __restrict__ k,
                        const float* __restrict__ off, __half* __restrict__ outop) {
    GDC_WAIT();   // q/k/off come from gemm3
    const int warp = (blockIdx.x * blockDim.x + threadIdx.x) >> 5;
    const int lane = threadIdx.x & 31;
    const int grp = lane >> 4;
    const int l16 = lane & 15;
    const int id = warp * 2 + grp;
    if (id < MM * NHEADS) {
        const int h = id & (NHEADS - 1);
        const int m = id >> 3;
        const int n = m % NN;
        const int b = m / NN;

        const int ch = h * HD + l16 * 8;
        const __half2* qp = reinterpret_cast<const __half2*>(q + (size_t)m * CC + ch);
        float2 qv[4];
#pragma unroll
        for (int j = 0; j < 4; j++) qv[j] = __half22float2(qp[j]);

        const int iy_n = n / WW;
        const int ix_n = n % WW;
        const float cy = -1.0f + 2.0f * (float)iy_n / (float)(HH - 1);
        const float cx = -1.0f + 2.0f * (float)ix_n / (float)(WW - 1);

        const float4* offv = reinterpret_cast<const float4*>(off + (size_t)m * 128 + h * (NPTS * 2));
        float4 o0 = offv[0], o1 = offv[1], o2 = offv[2], o3 = offv[3];
        float offr[16] = {o0.x, o0.y, o0.z, o0.w, o1.x, o1.y, o1.z, o1.w,
                          o2.x, o2.y, o2.z, o2.w, o3.x, o3.y, o3.z, o3.w};

        const __half* kb = k + (size_t)b * NN * CC;

        float sk[NPTS][8];
        float score[NPTS];
        const float scale = 0.08838834764831845f;

#pragma unroll
        for (int p = 0; p < NPTS; p++) {
            float l0 = cy + offr[2 * p + 0];
            float l1 = cx + offr[2 * p + 1];
            float ix = (l0 + 1.0f) * 0.5f * (float)(WW - 1);
            float iy = (l1 + 1.0f) * 0.5f * (float)(HH - 1);
            ix = fminf(fmaxf(ix, 0.0f), (float)(WW - 1));
            iy = fminf(fmaxf(iy, 0.0f), (float)(HH - 1));
            float x0f = floorf(ix), y0f = floorf(iy);
            float wx = ix - x0f, wy = iy - y0f;
            int x0 = (int)x0f, y0 = (int)y0f;
            int x1 = min(x0 + 1, WW - 1);
            int y1 = min(y0 + 1, HH - 1);

            uint4 r00 = *reinterpret_cast<const uint4*>(kb + (size_t)(y0 * WW + x0) * CC + ch);
            uint4 r01 = *reinterpret_cast<const uint4*>(kb + (size_t)(y0 * WW + x1) * CC + ch);
            uint4 r10 = *reinterpret_cast<const uint4*>(kb + (size_t)(y1 * WW + x0) * CC + ch);
            uint4 r11 = *reinterpret_cast<const uint4*>(kb + (size_t)(y1 * WW + x1) * CC + ch);
            const __half2* h00 = reinterpret_cast<const __half2*>(&r00);
            const __half2* h01 = reinterpret_cast<const __half2*>(&r01);
            const __half2* h10 = reinterpret_cast<const __half2*>(&r10);
            const __half2* h11 = reinterpret_cast<const __half2*>(&r11);

            float w00 = (1.0f - wy) * (1.0f - wx);
            float w01 = (1.0f - wy) * wx;
            float w10 = wy * (1.0f - wx);
            float w11 = wy * wx;

            float s = 0.0f;
#pragma unroll
            for (int j = 0; j < 4; j++) {
                float2 a = __half22float2(h00[j]);
                float2 c2 = __half22float2(h01[j]);
                float2 d2 = __half22float2(h10[j]);
                float2 e2 = __half22float2(h11[j]);
                float v0 = a.x * w00 + c2.x * w01 + d2.x * w10 + e2.x * w11;
                float v1 = a.y * w00 + c2.y * w01 + d2.y * w10 + e2.y * w11;
                sk[p][2 * j]     = v0;
                sk[p][2 * j + 1] = v1;
                s += qv[j].x * v0 + qv[j].y * v1;
            }
#pragma unroll
            for (int d = 8; d > 0; d >>= 1)
                s += __shfl_xor_sync(0xFFFFFFFFu, s, d);
            score[p] = s * scale;
        }

        float mx = score[0];
#pragma unroll
        for (int p = 1; p < NPTS; p++) mx = fmaxf(mx, score[p]);
        float denom = 0.0f;
        float e[NPTS];
#pragma unroll
        for (int p = 0; p < NPTS; p++) { e[p] = __expf(score[p] - mx); denom += e[p]; }
        float inv = 1.0f / denom;

        float av[8] = {0.f, 0.f, 0.f, 0.f, 0.f, 0.f, 0.f, 0.f};
#pragma unroll
        for (int p = 0; p < NPTS; p++) {
            float a = e[p] * inv;
#pragma unroll
            for (int j = 0; j < 8; j++) av[j] += a * sk[p][j];
        }

        __half hi[8];
#pragma unroll
        for (int j = 0; j < 8; j++) hi[j] = __float2half(av[j]);
        __half* rp = outop + (size_t)m * K1 + ch;
        *reinterpret_cast<uint4*>(rp) = *reinterpret_cast<uint4*>(hi);
    }
    GDC_LAUNCH();
}

// ---------------------------------------------------------------------------
extern "C" void kernel_launch(void* const* d_in, const int* in_sizes, int n_in,
                              void* d_out, int out_size) {
    const float* query = (const float*)d_in[0];
    const float* ref   = (const float*)d_in[1];
    const float* Wq    = (const float*)d_in[2];
    const float* bq    = (const float*)d_in[3];
    const float* Wkv   = (const float*)d_in[4];
    const float* bkv   = (const float*)d_in[5];
    const float* Woff  = (const float*)d_in[6];
    const float* boff  = (const float*)d_in[7];
    const float* Wout  = (const float*)d_in[8];
    const float* bout  = (const float*)d_in[9];
    float* outp = (float*)d_out;

    __half *aq, *ak, *bq_op, *bk_op, *bo_op, *bf_op, *qb, *kb;
    float *offp;
    cudaGetSymbolAddress((void**)&aq,    g_aq);
    cudaGetSymbolAddress((void**)&ak,    g_ak);
    cudaGetSymbolAddress((void**)&bq_op, g_bop_q);
    cudaGetSymbolAddress((void**)&bk_op, g_bop_k);
    cudaGetSymbolAddress((void**)&bo_op, g_bop_o);
    cudaGetSymbolAddress((void**)&bf_op, g_bop_f);
    cudaGetSymbolAddress((void**)&qb,    g_q);
    cudaGetSymbolAddress((void**)&kb,    g_k);
    cudaGetSymbolAddress((void**)&offp,  g_offp);

    cudaFuncSetAttribute(gemm3, cudaFuncAttributeMaxDynamicSharedMemorySize, SMEM_SZ);
    cudaFuncSetAttribute(gemm_out, cudaFuncAttributeMaxDynamicSharedMemorySize, SMEM_SZ);

    // 1. ALL conversions (weights + both activations) in one launch
    conv_all<<<4096 + 2 * ACT_BLKS, 256>>>(Wq, Wkv, Wout, Woff,
                                           bq_op, bk_op, bo_op, bf_op,
                                           query, ref, aq, ak);

    // PDL attribute: allow successors to launch under the predecessor's tail;
    // correctness gated by griddepcontrol.wait inside each kernel.
    cudaLaunchAttribute pdl[1];
    pdl[0].id = cudaLaunchAttributeProgrammaticStreamSerialization;
    pdl[0].val.programmaticStreamSerializationAllowed = 1;

    // 2. off (K3, A aliased) + q (K1) + k (K1) in one launch, 128-row tiles
    {
        cudaLaunchConfig_t cfg = {};
        cfg.gridDim = dim3(17 * MTILES);
        cfg.blockDim = dim3(256);
        cfg.dynamicSmemBytes = SMEM_SZ;
        cfg.attrs = pdl;
        cfg.numAttrs = 1;
        cudaLaunchKernelEx(&cfg, gemm3, (const __half*)aq, (const __half*)ak,
                           (const __half*)bq_op, (const __half*)bk_op, (const __half*)bf_op,
                           bq, bkv, boff, qb, kb, offp);
    }

    // 3. sampling + attention; 2 heads/warp; writes fp16 [Ah] operand into ak
    {
        int warps = (MM * NHEADS + 1) / 2;          // 43808
        int blocks = (warps * 32 + 255) / 256;      // 5476
        cudaLaunchConfig_t cfg = {};
        cfg.gridDim = dim3(blocks);
        cfg.blockDim = dim3(256);
        cfg.dynamicSmemBytes = 0;
        cfg.attrs = pdl;
        cfg.numAttrs = 1;
        cudaLaunchKernelEx(&cfg, sample_attn_kernel,
                           (const __half*)qb, (const __half*)kb, (const float*)offp, ak);
    }

    // 4. out = attn @ Wout + bout  (K1), 128-row tiles
    {
        cudaLaunchConfig_t cfg = {};
        cfg.gridDim = dim3(8, MTILES);
        cfg.blockDim = dim3(256);
        cfg.dynamicSmemBytes = SMEM_SZ;
        cfg.attrs = pdl;
        cfg.numAttrs = 1;
        cudaLaunchKernelEx(&cfg, gemm_out, (const __half*)ak, (const __half*)bo_op,
                           bout, outp);
    }
}

// round 17
// speedup vs baseline: 1.0283x; 1.0139x over previous
#include <cuda_runtime.h>
#include <cuda_fp16.h>
#include <math.h>
#include <cstdint>

// Problem constants
#define BB 8
#define HH 37
#define WW 37
#define NN (HH * WW)          // 1369
#define CC 1024
#define MM (BB * NN)          // 10952
#define NHEADS 8
#define HD 128
#define NPTS 8
#define K1 1024               // 1-term fp16 (q, k, out GEMMs)
#define K2 2048               // [Ah|Al] activation layout (off GEMM aliases term2 -> term0)
#define K3 3072               // off GEMM logical K (B = [Bh|Bh|Bl])
#define NCK1 (K1 / 64)        // 16
#define NCK3 (K3 / 64)        // 48
#define STAGES 3
#define STAGE_BYTES 32768     // A 16K + B 16K
#define SMEM_SZ (STAGES * STAGE_BYTES)   // 96KB -> 2 CTAs/SM (proven best)
#define MTILES 86             // ceil(MM/128)
#define ACT_BLKS 5476         // MM*128/256
#define WBLKS (3 * 1024 + 128)  // 3200: 1024 per square weight + 128 for Woff

// ---------------------------------------------------------------------------
// Scratch
// ---------------------------------------------------------------------------
__device__ __half g_aq[MM * K2];      // query [Ah|Al] (q uses K1 prefix, off aliases chunks)
__device__ __half g_ak[MM * K1];      // ref [Ah]; reused as attn [Ah]
__device__ __half g_bop_q[CC * K1];   // Wq [Bh]
__device__ __half g_bop_k[CC * K1];   // Wkv[:, :C] [Bh]
__device__ __half g_bop_o[CC * K1];   // Wout [Bh]
__device__ __half g_bop_f[128 * K3];  // Woff [Bh|Bh|Bl]
__device__ __half g_q[MM * CC];       // q in fp16
__device__ __half g_k[MM * CC];       // k in fp16
__device__ float  g_offp[MM * 128];

// ---------------------------------------------------------------------------
__device__ __forceinline__ uint32_t smem_u32(const void* p) {
    uint32_t a;
    asm("{ .reg .u64 t; cvta.to.shared.u64 t, %1; cvt.u32.u64 %0, t; }" : "=r"(a) : "l"(p));
    return a;
}
__device__ __forceinline__ void cp16(uint32_t dst, const void* src, bool valid) {
    int sz = valid ? 16 : 0;
    asm volatile("cp.async.cg.shared.global [%0], [%1], 16, %2;"
                 :: "r"(dst), "l"(src), "r"(sz) : "memory");
}
#define CP_COMMIT() asm volatile("cp.async.commit_group;" ::: "memory")
#define CP_WAIT1()  asm volatile("cp.async.wait_group 1;" ::: "memory")

__device__ __forceinline__ void ldsm4(uint32_t* r, uint32_t addr) {
    asm volatile("ldmatrix.sync.aligned.m8n8.x4.shared.b16 {%0,%1,%2,%3}, [%4];"
                 : "=r"(r[0]), "=r"(r[1]), "=r"(r[2]), "=r"(r[3]) : "r"(addr));
}
__device__ __forceinline__ void mma16816(float* c, const uint32_t* a, const uint32_t* b) {
    asm volatile(
        "mma.sync.aligned.m16n8k16.row.col.f32.f16.f16.f32 "
        "{%0,%1,%2,%3},{%4,%5,%6,%7},{%8,%9},{%0,%1,%2,%3};"
        : "+f"(c[0]), "+f"(c[1]), "+f"(c[2]), "+f"(c[3])
        : "r"(a[0]), "r"(a[1]), "r"(a[2]), "r"(a[3]), "r"(b[0]), "r"(b[1]));
}

// ---------------------------------------------------------------------------
// GEMM body (R13-proven): CTA 128x128, 8 warps 64x32, 3-stage cp.async,
// ONE sync per chunk. ka_wrap: A-chunk aliasing (off GEMM term2 -> term0).
// ---------------------------------------------------------------------------
template <typename OutT>
__device__ __forceinline__
void gemm_body(const __half* __restrict__ A, int lda,
               const __half* __restrict__ B, int ldb,
               const float* __restrict__ bias, OutT* __restrict__ C,
               int ldc, int m0, int col0, int nchunk, int ka_wrap, char* smem) {
    const uint32_t sb0 = smem_u32(smem);
    const int tid = threadIdx.x, wid = tid >> 5, lane = tid & 31;
    const __half* Bc0 = B + (size_t)col0 * ldb;

    auto load_stage = [&](int ck, int stage) {
        const uint32_t sa = sb0 + stage * STAGE_BYTES;
        const int ca = (ck >= ka_wrap) ? ck - ka_wrap : ck;
        const __half* Ac = A + ca * 64;
        const __half* Bc = Bc0 + ck * 64;
#pragma unroll
        for (int i = 0; i < 4; i++) {
            int id = tid + i * 256;
            int row = id >> 3, c16 = id & 7;
            int gr = m0 + row;
            bool v = gr < MM;
            int grc = v ? gr : (MM - 1);
            uint32_t dst = sa + row * 128 + (((uint32_t)c16 ^ (row & 7)) << 4);
            cp16(dst, Ac + (size_t)grc * lda + c16 * 8, v);
        }
#pragma unroll
        for (int i = 0; i < 4; i++) {
            int id = tid + i * 256;
            int row = id >> 3, c16 = id & 7;
            uint32_t dst = sa + 16384 + row * 128 + (((uint32_t)c16 ^ (row & 7)) << 4);
            cp16(dst, Bc + (size_t)row * ldb + c16 * 8, true);
        }
        CP_COMMIT();
    };

    float acc[4][4][4];
#pragma unroll
    for (int mt = 0; mt < 4; mt++)
#pragma unroll
        for (int nt = 0; nt < 4; nt++)
#pragma unroll
            for (int j = 0; j < 4; j++) acc[mt][nt][j] = 0.0f;

    load_stage(0, 0);
    load_stage(1, 1);

    const int wm = (wid & 1) * 64;
    const int wn = (wid >> 1) * 32;

    for (int c = 0; c < nchunk; c++) {
        CP_WAIT1();
        __syncthreads();   // single barrier; also protects buffer reuse
        if (c + 2 < nchunk) load_stage(c + 2, (c + 2) % STAGES);
        else CP_COMMIT();

        const uint32_t sa = sb0 + (c % STAGES) * STAGE_BYTES;
        const uint32_t sbB = sa + 16384;

#pragma unroll
        for (int ks = 0; ks < 4; ks++) {
            uint32_t af[4][4];
#pragma unroll
            for (int mt = 0; mt < 4; mt++) {
                int row = wm + mt * 16 + (lane & 15);
                uint32_t c16 = (uint32_t)(ks * 2 + (lane >> 4)) ^ (row & 7);
                ldsm4(af[mt], sa + row * 128 + (c16 << 4));
            }
            uint32_t bf[4][2];
#pragma unroll
            for (int nt2 = 0; nt2 < 2; nt2++) {
                int group = lane >> 3;
                int nrow = wn + nt2 * 16 + (group >> 1) * 8 + (lane & 7);
                uint32_t c16 = (uint32_t)(ks * 2 + (group & 1)) ^ (nrow & 7);
                uint32_t r[4];
                ldsm4(r, sbB + nrow * 128 + (c16 << 4));
                bf[nt2 * 2][0] = r[0]; bf[nt2 * 2][1] = r[1];
                bf[nt2 * 2 + 1][0] = r[2]; bf[nt2 * 2 + 1][1] = r[3];
            }
#pragma unroll
            for (int mt = 0; mt < 4; mt++)
#pragma unroll
                for (int nt = 0; nt < 4; nt++)
                    mma16816(acc[mt][nt], af[mt], bf[nt]);
        }
    }
    __syncthreads();

    const int lr = lane >> 2, lc = (lane & 3) * 2;
#pragma unroll
    for (int mt = 0; mt < 4; mt++) {
#pragma unroll
        for (int nt = 0; nt < 4; nt++) {
            int r0 = m0 + wm + mt * 16 + lr;
            int cb = col0 + wn + nt * 8 + lc;
            float b0 = bias[cb], b1 = bias[cb + 1];
            if (r0 < MM) {
                if (sizeof(OutT) == 2) {
                    __half2 v = __floats2half2_rn(acc[mt][nt][0] + b0, acc[mt][nt][1] + b1);
                    *reinterpret_cast<__half2*>((__half*)C + (size_t)r0 * ldc + cb) = v;
                } else {
                    float2 v = make_float2(acc[mt][nt][0] + b0, acc[mt][nt][1] + b1);
                    *reinterpret_cast<float2*>((float*)C + (size_t)r0 * ldc + cb) = v;
                }
            }
            int r1 = r0 + 8;
            if (r1 < MM) {
                if (sizeof(OutT) == 2) {
                    __half2 v = __floats2half2_rn(acc[mt][nt][2] + b0, acc[mt][nt][3] + b1);
                    *reinterpret_cast<__half2*>((__half*)C + (size_t)r1 * ldc + cb) = v;
                } else {
                    float2 v = make_float2(acc[mt][nt][2] + b0, acc[mt][nt][3] + b1);
                    *reinterpret_cast<float2*>((float*)C + (size_t)r1 * ldc + cb) = v;
                }
            }
        }
    }
}

// Merged off + q + k GEMM. t = bx / MTILES:
// t == 0: off (K3 logical, A aliased mod 32); t in [1,9): q; t in [9,17): k.
__global__ __launch_bounds__(256)
void gemm3(const __half* __restrict__ Aq, const __half* __restrict__ Ak,
           const __half* __restrict__ Bq, const __half* __restrict__ Bk,
           const __half* __restrict__ Bf,
           const float* __restrict__ bq, const float* __restrict__ bkv,
           const float* __restrict__ boff,
           __half* __restrict__ Cq, __half* __restrict__ Ck, float* __restrict__ Coff) {
    extern __shared__ char smem[];
    const int bx = blockIdx.x;
    const int t = bx / MTILES;
    const int m0 = (bx % MTILES) * 128;
    if (t == 0) {
        gemm_body<float>(Aq, K2, Bf, K3, boff, Coff, 128, m0, 0, NCK3, 32, smem);
    } else if (t < 9) {
        gemm_body<__half>(Aq, K2, Bq, K1, bq, Cq, CC, m0, (t - 1) * 128, NCK1, 9999, smem);
    } else {
        gemm_body<__half>(Ak, K1, Bk, K1, bkv, Ck, CC, m0, (t - 9) * 128, NCK1, 9999, smem);
    }
}

// Final GEMM: out = attn(K1) @ Wout + bout
__global__ __launch_bounds__(256)
void gemm_out(const __half* __restrict__ A, const __half* __restrict__ B,
              const float* __restrict__ bias, float* __restrict__ C) {
    extern __shared__ char smem[];
    gemm_body<float>(A, K1, B, K1, bias, C, CC, blockIdx.y * 128, blockIdx.x * 128,
                     NCK1, 9999, smem);
}

// ---------------------------------------------------------------------------
// ALL conversions in one launch. Grid = WBLKS (weights) + 2*ACT_BLKS (acts).
// Weight blocks: z<3 get 1024 blocks each; Woff exactly 128 (4 nt x 32 kt).
// ---------------------------------------------------------------------------
__global__ __launch_bounds__(256)
void conv_all(const float* __restrict__ Wq, const float* __restrict__ Wkv,
              const float* __restrict__ Wout, const float* __restrict__ Woff,
              __half* __restrict__ Oq, __half* __restrict__ Ok,
              __half* __restrict__ Oo, __half* __restrict__ Of,
              const float* __restrict__ query, const float* __restrict__ ref,
              __half* __restrict__ aq, __half* __restrict__ ak) {
    const int bid = blockIdx.x;
    if (bid < WBLKS) {
        int z, r;
        if (bid < 3072) { z = bid >> 10; r = bid & 1023; }
        else            { z = 3;         r = bid - 3072; }     // 128 blocks
        const int nt = (z == 3) ? (r & 3) : (r & 31);
        const int kt = (z == 3) ? (r >> 2) : (r >> 5);
        const float* W;
        int ldw, nvalid;
        if (z == 0)      { W = Wq;   ldw = CC;     nvalid = CC; }
        else if (z == 1) { W = Wkv;  ldw = 2 * CC; nvalid = CC; }
        else if (z == 2) { W = Wout; ldw = CC;     nvalid = CC; }
        else             { W = Woff; ldw = 128;    nvalid = 128; }

        __shared__ float t[32][33];
        const int tx = threadIdx.x & 31, ty = threadIdx.x >> 5;
        const int n0 = nt * 32, k0 = kt * 32;
#pragma unroll
        for (int j = ty; j < 32; j += 8) {
            int n = n0 + tx, k = k0 + j;
            t[j][tx] = (n < nvalid) ? W[(size_t)k * ldw + n] : 0.0f;
        }
        __syncthreads();
#pragma unroll
        for (int j = ty; j < 32; j += 8) {
            int n = n0 + j, k = k0 + tx;
            float v = t[tx][j];
            __half h = __float2half(v);
            if (z == 0)      { Oq[(size_t)n * K1 + k] = h; }
            else if (z == 1) { Ok[(size_t)n * K1 + k] = h; }
            else if (z == 2) { Oo[(size_t)n * K1 + k] = h; }
            else             { __half l = __float2half(v - __half2float(h));
                               __half* row = Of + (size_t)n * K3;
                               row[k] = h; row[k + 1024] = h; row[k + 2048] = l; }
        }
    } else {
        const int j = bid - WBLKS;
        const bool isq = j < ACT_BLKS;
        const int blk = isq ? j : j - ACT_BLKS;
        size_t i = (size_t)blk * 256 + threadIdx.x;
        if (i >= (size_t)MM * 128) return;
        size_t rrow = i >> 7;
        int c8 = (int)(i & 127) * 8;
        const float* A = isq ? query : ref;
        const float4* p = reinterpret_cast<const float4*>(A + rrow * CC + c8);
        float4 v0 = p[0], v1 = p[1];
        float vv[8] = {v0.x, v0.y, v0.z, v0.w, v1.x, v1.y, v1.z, v1.w};
        __half hi[8], lo[8];
#pragma unroll
        for (int jj = 0; jj < 8; jj++) {
            hi[jj] = __float2half(vv[jj]);
            lo[jj] = __float2half(vv[jj] - __half2float(hi[jj]));
        }
        if (isq) {
            __half* rp = aq + rrow * K2;
            *reinterpret_cast<uint4*>(rp + c8)        = *reinterpret_cast<uint4*>(hi);
            *reinterpret_cast<uint4*>(rp + c8 + 1024) = *reinterpret_cast<uint4*>(lo);
        } else {
            __half* rp = ak + rrow * K1;
            *reinterpret_cast<uint4*>(rp + c8) = *reinterpret_cast<uint4*>(hi);
        }
    }
}

// ---------------------------------------------------------------------------
// Sampling + attention (R13-proven): 2 heads/warp, 16 lanes/head, 8 ch/lane.
// Writes fp16 attn operand [Ah] (stride K1) directly.
// ---------------------------------------------------------------------------
__global__ __launch_bounds__(256)
void sample_attn_kernel(const __half* __restrict__ q, const __half* __restrict__ k,
                        const float* __restrict__ off, __half* __restrict__ outop) {
    const int warp = (blockIdx.x * blockDim.x + threadIdx.x) >> 5;
    const int lane = threadIdx.x & 31;
    const int grp = lane >> 4;
    const int l16 = lane & 15;
    const int id = warp * 2 + grp;
    if (id >= MM * NHEADS) return;

    const int h = id & (NHEADS - 1);
    const int m = id >> 3;
    const int n = m % NN;
    const int b = m / NN;

    const int ch = h * HD + l16 * 8;
    const __half2* qp = reinterpret_cast<const __half2*>(q + (size_t)m * CC + ch);
    float2 qv[4];
#pragma unroll
    for (int j = 0; j < 4; j++) qv[j] = __half22float2(qp[j]);

    const int iy_n = n / WW;
    const int ix_n = n % WW;
    const float cy = -1.0f + 2.0f * (float)iy_n / (float)(HH - 1);
    const float cx = -1.0f + 2.0f * (float)ix_n / (float)(WW - 1);

    const float4* offv = reinterpret_cast<const float4*>(off + (size_t)m * 128 + h * (NPTS * 2));
    float4 o0 = offv[0], o1 = offv[1], o2 = offv[2], o3 = offv[3];
    float offr[16] = {o0.x, o0.y, o0.z, o0.w, o1.x, o1.y, o1.z, o1.w,
                      o2.x, o2.y, o2.z, o2.w, o3.x, o3.y, o3.z, o3.w};

    const __half* kb = k + (size_t)b * NN * CC;

    float sk[NPTS][8];
    float score[NPTS];
    const float scale = 0.08838834764831845f;

#pragma unroll
    for (int p = 0; p < NPTS; p++) {
        float l0 = cy + offr[2 * p + 0];
        float l1 = cx + offr[2 * p + 1];
        float ix = (l0 + 1.0f) * 0.5f * (float)(WW - 1);
        float iy = (l1 + 1.0f) * 0.5f * (float)(HH - 1);
        ix = fminf(fmaxf(ix, 0.0f), (float)(WW - 1));
        iy = fminf(fmaxf(iy, 0.0f), (float)(HH - 1));
        float x0f = floorf(ix), y0f = floorf(iy);
        float wx = ix - x0f, wy = iy - y0f;
        int x0 = (int)x0f, y0 = (int)y0f;
        int x1 = min(x0 + 1, WW - 1);
        int y1 = min(y0 + 1, HH - 1);

        uint4 r00 = *reinterpret_cast<const uint4*>(kb + (size_t)(y0 * WW + x0) * CC + ch);
        uint4 r01 = *reinterpret_cast<const uint4*>(kb + (size_t)(y0 * WW + x1) * CC + ch);
        uint4 r10 = *reinterpret_cast<const uint4*>(kb + (size_t)(y1 * WW + x0) * CC + ch);
        uint4 r11 = *reinterpret_cast<const uint4*>(kb + (size_t)(y1 * WW + x1) * CC + ch);
        const __half2* h00 = reinterpret_cast<const __half2*>(&r00);
        const __half2* h01 = reinterpret_cast<const __half2*>(&r01);
        const __half2* h10 = reinterpret_cast<const __half2*>(&r10);
        const __half2* h11 = reinterpret_cast<const __half2*>(&r11);

        float w00 = (1.0f - wy) * (1.0f - wx);
        float w01 = (1.0f - wy) * wx;
        float w10 = wy * (1.0f - wx);
        float w11 = wy * wx;

        float s = 0.0f;
#pragma unroll
        for (int j = 0; j < 4; j++) {
            float2 a = __half22float2(h00[j]);
            float2 c2 = __half22float2(h01[j]);
            float2 d2 = __half22float2(h10[j]);
            float2 e2 = __half22float2(h11[j]);
            float v0 = a.x * w00 + c2.x * w01 + d2.x * w10 + e2.x * w11;
            float v1 = a.y * w00 + c2.y * w01 + d2.y * w10 + e2.y * w11;
            sk[p][2 * j]     = v0;
            sk[p][2 * j + 1] = v1;
            s += qv[j].x * v0 + qv[j].y * v1;
        }
#pragma unroll
        for (int d = 8; d > 0; d >>= 1)
            s += __shfl_xor_sync(0xFFFFFFFFu, s, d);
        score[p] = s * scale;
    }

    float mx = score[0];
#pragma unroll
    for (int p = 1; p < NPTS; p++) mx = fmaxf(mx, score[p]);
    float denom = 0.0f;
    float e[NPTS];
#pragma unroll
    for (int p = 0; p < NPTS; p++) { e[p] = __expf(score[p] - mx); denom += e[p]; }
    float inv = 1.0f / denom;

    float av[8] = {0.f, 0.f, 0.f, 0.f, 0.f, 0.f, 0.f, 0.f};
#pragma unroll
    for (int p = 0; p < NPTS; p++) {
        float a = e[p] * inv;
#pragma unroll
        for (int j = 0; j < 8; j++) av[j] += a * sk[p][j];
    }

    __half hi[8];
#pragma unroll
    for (int j = 0; j < 8; j++) hi[j] = __float2half(av[j]);
    __half* rp = outop + (size_t)m * K1 + ch;
    *reinterpret_cast<uint4*>(rp) = *reinterpret_cast<uint4*>(hi);
}

// ---------------------------------------------------------------------------
extern "C" void kernel_launch(void* const* d_in, const int* in_sizes, int n_in,
                              void* d_out, int out_size) {
    const float* query = (const float*)d_in[0];
    const float* ref   = (const float*)d_in[1];
    const float* Wq    = (const float*)d_in[2];
    const float* bq    = (const float*)d_in[3];
    const float* Wkv   = (const float*)d_in[4];
    const float* bkv   = (const float*)d_in[5];
    const float* Woff  = (const float*)d_in[6];
    const float* boff  = (const float*)d_in[7];
    const float* Wout  = (const float*)d_in[8];
    const float* bout  = (const float*)d_in[9];
    float* outp = (float*)d_out;

    __half *aq, *ak, *bq_op, *bk_op, *bo_op, *bf_op, *qb, *kb;
    float *offp;
    cudaGetSymbolAddress((void**)&aq,    g_aq);
    cudaGetSymbolAddress((void**)&ak,    g_ak);
    cudaGetSymbolAddress((void**)&bq_op, g_bop_q);
    cudaGetSymbolAddress((void**)&bk_op, g_bop_k);
    cudaGetSymbolAddress((void**)&bo_op, g_bop_o);
    cudaGetSymbolAddress((void**)&bf_op, g_bop_f);
    cudaGetSymbolAddress((void**)&qb,    g_q);
    cudaGetSymbolAddress((void**)&kb,    g_k);
    cudaGetSymbolAddress((void**)&offp,  g_offp);

    cudaFuncSetAttribute(gemm3, cudaFuncAttributeMaxDynamicSharedMemorySize, SMEM_SZ);
    cudaFuncSetAttribute(gemm_out, cudaFuncAttributeMaxDynamicSharedMemorySize, SMEM_SZ);

    // 1. ALL conversions (weights + both activations) in one launch
    conv_all<<<WBLKS + 2 * ACT_BLKS, 256>>>(Wq, Wkv, Wout, Woff,
                                            bq_op, bk_op, bo_op, bf_op,
                                            query, ref, aq, ak);

    // 2. off (K3, A aliased) + q (K1) + k (K1) in one launch, 128-row tiles
    gemm3<<<17 * MTILES, 256, SMEM_SZ>>>(aq, ak, bq_op, bk_op, bf_op,
                                         bq, bkv, boff, qb, kb, offp);

    // 3. sampling + attention; 2 heads/warp; writes fp16 [Ah] operand into ak
    {
        int warps = (MM * NHEADS + 1) / 2;          // 43808
        int blocks = (warps * 32 + 255) / 256;      // 5476
        sample_attn_kernel<<<blocks, 256>>>(qb, kb, offp, ak);
    }

    // 4. out = attn @ Wout + bout  (K1), 128-row tiles
    gemm_out<<<dim3(8, MTILES), 256, SMEM_SZ>>>(ak, bo_op, bout, outp);
}